// round 4
// baseline (speedup 1.0000x reference)
#include <cuda_runtime.h>
#include <math.h>

#define NB 2048

typedef unsigned long long u64;

// ---------------- scratch ----------------
__device__ float g_buf1[NB*16*28*28];
__device__ float g_buf2[NB*16*28*28];
__device__ float g_buf3[NB*16*14*14];
__device__ float g_buf4[NB*32*14*14];
__device__ float g_buf5[NB*32*14*14];
__device__ float g_buf6[NB*32*7*7];
__device__ float g_buf7[NB*64*7*7];
__device__ float g_buf8[NB*64*7*7];
__device__ float g_buf9[NB*64*4*4];
__device__ float g_rk1[16*1*9];
__device__ float g_rk2[16*16*9];
__device__ float g_rk3[32*16*9];
__device__ float g_sum[224];
__device__ float g_sumsq[224];
__device__ float g_scale[224];
__device__ float g_shift[224];
__device__ int   g_cnt[224];
__device__ float g_nms;

#define ST1 0
#define ST2 16
#define ST3 32
#define ST4 64
#define ST5 96
#define ST6 160

// ---------------- packed fp32x2 helpers ----------------
__device__ __forceinline__ u64 pack2(float lo, float hi) {
    u64 r; asm("mov.b64 %0, {%1, %2};" : "=l"(r) : "f"(lo), "f"(hi)); return r;
}
__device__ __forceinline__ u64 fma2(u64 a, u64 b, u64 c) {
    u64 d; asm("fma.rn.f32x2 %0, %1, %2, %3;" : "=l"(d) : "l"(a), "l"(b), "l"(c)); return d;
}
__device__ __forceinline__ void unpack2(u64 v, float& lo, float& hi) {
    asm("mov.b64 {%0, %1}, %2;" : "=f"(lo), "=f"(hi) : "l"(v));
}

__device__ __forceinline__ float warp_sum(float v) {
    #pragma unroll
    for (int o = 16; o > 0; o >>= 1) v += __shfl_xor_sync(0xffffffffu, v, o);
    return v;
}

// ---------------- build rotated kernels + zero accumulators ----------------
__global__ void k_build_rk(const float* __restrict__ w1, const float* __restrict__ w2,
                           const float* __restrict__ w3) {
    int idx = blockIdx.x * blockDim.x + threadIdx.x;
    if (idx < 224) { g_sum[idx] = 0.f; g_sumsq[idx] = 0.f; g_cnt[idx] = 0; }
    if (idx == 0) g_nms = 0.f;
    if (idx >= 16 + 256 + 512) return;
    float local[9];
    #pragma unroll
    for (int k = 0; k < 9; k++) local[k] = 0.f;

    int i, a, ic = 0, which;
    if (idx < 16)       { which = 0; i = idx >> 1; a = idx & 1; }
    else if (idx < 272) { int e = idx - 16;  which = 1; ic = e & 15; a = (e >> 4) & 1; i = e >> 5; }
    else                { int e = idx - 272; which = 2; ic = e & 15; a = (e >> 4) & 3; i = e >> 6; }

    double th = 0.78539816339744831 * (double)i;
    double ct = cos(th), st = sin(th);

    int ics = ic;
    if (which != 0) {
        int bnew = ic >> 1, sub = ic & 1;
        int bsrc = ((bnew - i) % 8 + 8) % 8;
        ics = bsrc * 2 + sub;
    }
    const float* src;
    if (which == 0)      src = w1 + a * 9;
    else if (which == 1) src = w2 + (a * 16 + ics) * 9;
    else                 src = w3 + (a * 16 + ics) * 9;

    #pragma unroll
    for (int t = 0; t < 9; t++) {
        int row = t / 3, col = t % 3;
        double x = (double)(col - 1), y = (double)(row - 1);
        int xr = (int)llrint(x * ct + y * st);
        int yr = (int)llrint(-x * st + y * ct);
        local[(1 - yr) * 3 + (1 - xr)] += src[t];
    }

    float* dst;
    if (which == 0)      dst = g_rk1 + (i * 2 + a) * 9;
    else if (which == 1) dst = g_rk2 + ((i * 2 + a) * 16 + ic) * 9;
    else                 dst = g_rk3 + ((i * 4 + a) * 16 + ic) * 9;
    #pragma unroll
    for (int k = 0; k < 9; k++) dst[k] = local[k];
}

// ---------------- conv3x3, lane->gy mapping, odd WPAD (conflict-free LDS) ----------
template<int CIN, int COUT, int H, int W, int IMGS, int WPAD, int IMG_PAD, bool BN_IN>
__global__ __launch_bounds__(224, 3)
void conv3x3v3(const float* __restrict__ in, const float* __restrict__ wt,
               const float* __restrict__ scale, const float* __restrict__ shift,
               float* __restrict__ out) {
    constexpr int G = (W + 3) / 4;
    constexpr int HP = H + 2;
    constexpr int PLANE = HP * WPAD;
    constexpr int IMG_STRIDE = CIN * PLANE + IMG_PAD;
    constexpr int OCG = COUT / 8;
    constexpr int ITEMS = IMGS * OCG * G * H;
    constexpr int P = H * W;
    constexpr int WFLOATS = CIN * COUT * 9;

    extern __shared__ float sm[];
    float* s_in = sm;                        // IMGS * IMG_STRIDE
    float* s_w  = sm + IMGS * IMG_STRIDE;    // [ic][oc/2][9] float2 pairs

    const int b0 = blockIdx.x * IMGS;
    const int tid = threadIdx.x;

    for (int idx = tid; idx < WFLOATS; idx += 224) {
        int h = idx & 1; int u = idx >> 1;
        int t = u % 9; u /= 9;
        int op = u % (COUT / 2); int ic = u / (COUT / 2);
        s_w[idx] = wt[((2 * op + h) * CIN + ic) * 9 + t];
    }
    for (int idx = tid; idx < IMGS * CIN * HP * WPAD; idx += 224) {
        int c = idx % WPAD; int t = idx / WPAD;
        int r = t % HP; t /= HP;
        int ic = t % CIN; int img = t / CIN;
        float v = 0.f;
        if (r >= 1 && r <= H && c >= 1 && c <= W) {
            v = in[(((size_t)(b0 + img) * CIN + ic) * H + (r - 1)) * W + (c - 1)];
            if (BN_IN) v = fmaxf(0.f, fmaf(v, scale[ic], shift[ic]));
        }
        s_in[img * IMG_STRIDE + ic * PLANE + r * WPAD + c] = v;
    }
    __syncthreads();

    const u64* w64 = (const u64*)s_w;

    for (int item = tid; item < ITEMS; item += 224) {
        int gy = item % H; int t = item / H;
        int gx = t % G; t /= G;
        int img = t % IMGS; int ocg = t / IMGS;

        u64 acc[4][4];
        #pragma unroll
        for (int px = 0; px < 4; px++)
            #pragma unroll
            for (int op = 0; op < 4; op++) acc[px][op] = 0ull;

        const float* ibase = s_in + img * IMG_STRIDE + gy * WPAD + 4 * gx;
        const u64* wbase = w64 + (size_t)ocg * 4 * 9;

        #pragma unroll 1
        for (int ic = 0; ic < CIN; ic++) {
            const float* ip = ibase + ic * PLANE;
            const u64* wrow = wbase + (size_t)ic * (COUT / 2) * 9;
            #pragma unroll
            for (int r = 0; r < 3; r++) {
                float i0 = ip[r * WPAD + 0], i1 = ip[r * WPAD + 1], i2 = ip[r * WPAD + 2];
                float i3 = ip[r * WPAD + 3], i4 = ip[r * WPAD + 4], i5 = ip[r * WPAD + 5];
                u64 d0 = pack2(i0, i0), d1 = pack2(i1, i1), d2 = pack2(i2, i2);
                u64 d3 = pack2(i3, i3), d4 = pack2(i4, i4), d5 = pack2(i5, i5);
                #pragma unroll
                for (int op = 0; op < 4; op++) {
                    const u64* w9 = wrow + op * 9 + r * 3;
                    u64 w;
                    w = w9[0];
                    acc[0][op] = fma2(d0, w, acc[0][op]);
                    acc[1][op] = fma2(d1, w, acc[1][op]);
                    acc[2][op] = fma2(d2, w, acc[2][op]);
                    acc[3][op] = fma2(d3, w, acc[3][op]);
                    w = w9[1];
                    acc[0][op] = fma2(d1, w, acc[0][op]);
                    acc[1][op] = fma2(d2, w, acc[1][op]);
                    acc[2][op] = fma2(d3, w, acc[2][op]);
                    acc[3][op] = fma2(d4, w, acc[3][op]);
                    w = w9[2];
                    acc[0][op] = fma2(d2, w, acc[0][op]);
                    acc[1][op] = fma2(d3, w, acc[1][op]);
                    acc[2][op] = fma2(d4, w, acc[2][op]);
                    acc[3][op] = fma2(d5, w, acc[3][op]);
                }
            }
        }

        float* outb = out + ((size_t)(b0 + img) * COUT + ocg * 8) * P + gy * W + 4 * gx;
        if (W % 4 == 0) {
            #pragma unroll
            for (int op = 0; op < 4; op++) {
                float l0, h0, l1, h1, l2, h2, l3, h3;
                unpack2(acc[0][op], l0, h0); unpack2(acc[1][op], l1, h1);
                unpack2(acc[2][op], l2, h2); unpack2(acc[3][op], l3, h3);
                *(float4*)(outb + (2 * op) * P)     = make_float4(l0, l1, l2, l3);
                *(float4*)(outb + (2 * op + 1) * P) = make_float4(h0, h1, h2, h3);
            }
        } else if (W % 2 == 0) {
            #pragma unroll
            for (int op = 0; op < 4; op++) {
                float l0, h0, l1, h1, l2, h2, l3, h3;
                unpack2(acc[0][op], l0, h0); unpack2(acc[1][op], l1, h1);
                unpack2(acc[2][op], l2, h2); unpack2(acc[3][op], l3, h3);
                *(float2*)(outb + (2 * op) * P)     = make_float2(l0, l1);
                *(float2*)(outb + (2 * op + 1) * P) = make_float2(h0, h1);
                if (4 * gx + 3 < W) {
                    *(float2*)(outb + (2 * op) * P + 2)     = make_float2(l2, l3);
                    *(float2*)(outb + (2 * op + 1) * P + 2) = make_float2(h2, h3);
                }
            }
        } else {
            int nvalid = W - 4 * gx; if (nvalid > 4) nvalid = 4;
            #pragma unroll
            for (int op = 0; op < 4; op++) {
                #pragma unroll
                for (int px = 0; px < 4; px++) {
                    if (px < nvalid) {
                        float lo, hi;
                        unpack2(acc[px][op], lo, hi);
                        outb[(2 * op) * P + px]     = lo;
                        outb[(2 * op + 1) * P + px] = hi;
                    }
                }
            }
        }
    }
}

// ---------------- stats + last-block finalize ----------------
__global__ void k_statsfin4(const float* __restrict__ x, float* __restrict__ sum,
                            float* __restrict__ sumsq, int* __restrict__ cnt,
                            const float* __restrict__ gamma, const float* __restrict__ beta,
                            float* __restrict__ scale, float* __restrict__ shift,
                            int C, int HW4, int gmod, float invN) {
    int c = blockIdx.y;
    float s = 0.f, s2 = 0.f;
    int N4 = NB * HW4;
    const float4* xp = (const float4*)x;
    for (int idx = blockIdx.x * blockDim.x + threadIdx.x; idx < N4;
         idx += gridDim.x * blockDim.x) {
        int b = idx / HW4; int p = idx - b * HW4;
        float4 v = xp[(size_t)(b * C + c) * HW4 + p];
        s += (v.x + v.y) + (v.z + v.w);
        s2 = fmaf(v.x, v.x, s2); s2 = fmaf(v.y, v.y, s2);
        s2 = fmaf(v.z, v.z, s2); s2 = fmaf(v.w, v.w, s2);
    }
    s = warp_sum(s); s2 = warp_sum(s2);
    __shared__ float sh[2][8];
    int lane = threadIdx.x & 31, wid = threadIdx.x >> 5;
    if (lane == 0) { sh[0][wid] = s; sh[1][wid] = s2; }
    __syncthreads();
    if (threadIdx.x == 0) {
        float a = 0.f, b2 = 0.f;
        #pragma unroll
        for (int i = 0; i < 8; i++) { a += sh[0][i]; b2 += sh[1][i]; }
        atomicAdd(&sum[c], a); atomicAdd(&sumsq[c], b2);
        __threadfence();
        int t = atomicAdd(&cnt[c], 1);
        if (t == (int)gridDim.x - 1) {
            __threadfence();
            float Ssum = *((volatile float*)&sum[c]);
            float Ssq  = *((volatile float*)&sumsq[c]);
            float mean = Ssum * invN;
            float var  = Ssq * invN - mean * mean;
            float sc = gamma[c % gmod] * rsqrtf(var + 1e-5f);
            scale[c] = sc;
            shift[c] = beta[c % gmod] - mean * sc;
        }
    }
}

__global__ void k_statsfin(const float* __restrict__ x, float* __restrict__ sum,
                           float* __restrict__ sumsq, int* __restrict__ cnt,
                           const float* __restrict__ gamma, const float* __restrict__ beta,
                           float* __restrict__ scale, float* __restrict__ shift,
                           int C, int HW, int gmod, float invN) {
    int c = blockIdx.y;
    float s = 0.f, s2 = 0.f;
    int N = NB * HW;
    for (int idx = blockIdx.x * blockDim.x + threadIdx.x; idx < N;
         idx += gridDim.x * blockDim.x) {
        int b = idx / HW; int p = idx - b * HW;
        float v = x[((size_t)b * C + c) * HW + p];
        s += v; s2 = fmaf(v, v, s2);
    }
    s = warp_sum(s); s2 = warp_sum(s2);
    __shared__ float sh[2][8];
    int lane = threadIdx.x & 31, wid = threadIdx.x >> 5;
    if (lane == 0) { sh[0][wid] = s; sh[1][wid] = s2; }
    __syncthreads();
    if (threadIdx.x == 0) {
        float a = 0.f, b2 = 0.f;
        #pragma unroll
        for (int i = 0; i < 8; i++) { a += sh[0][i]; b2 += sh[1][i]; }
        atomicAdd(&sum[c], a); atomicAdd(&sumsq[c], b2);
        __threadfence();
        int t = atomicAdd(&cnt[c], 1);
        if (t == (int)gridDim.x - 1) {
            __threadfence();
            float Ssum = *((volatile float*)&sum[c]);
            float Ssq  = *((volatile float*)&sumsq[c]);
            float mean = Ssum * invN;
            float var  = Ssq * invN - mean * mean;
            float sc = gamma[c % gmod] * rsqrtf(var + 1e-5f);
            scale[c] = sc;
            shift[c] = beta[c % gmod] - mean * sc;
        }
    }
}

// ---------------- BN + ReLU + 2x2 maxpool ----------------
template<int C, int H, int W, int PAD>
__global__ void k_pool(const float* __restrict__ in, const float* __restrict__ scale,
                       const float* __restrict__ shift, float* __restrict__ out) {
    constexpr int HO = (H + 2 * PAD) / 2, WO = (W + 2 * PAD) / 2;
    int total = NB * C * HO * WO;
    for (int idx = blockIdx.x * blockDim.x + threadIdx.x; idx < total;
         idx += gridDim.x * blockDim.x) {
        int wo = idx % WO; int t = idx / WO;
        int ho = t % HO; t /= HO;
        int c = t % C; int b = t / C;
        const float* p = in + ((size_t)b * C + c) * (H * W);
        float sc = scale[c], sh = shift[c];
        float m = -1e30f;
        int iy0 = ho * 2 - PAD, ix0 = wo * 2 - PAD;
        #pragma unroll
        for (int dy = 0; dy < 2; dy++) {
            int iy = iy0 + dy; if (iy < 0 || iy >= H) continue;
            #pragma unroll
            for (int dx = 0; dx < 2; dx++) {
                int ix = ix0 + dx; if (ix < 0 || ix >= W) continue;
                float v = fmaxf(0.f, fmaf(p[iy * W + ix], sc, sh));
                if (v > m) m = v;
            }
        }
        out[idx] = m;
    }
}

// ---------------- NMS (rotation-minor channel view c = c1*8 + j) ----------------
__global__ void k_nms(const float* __restrict__ x, const float* __restrict__ scale,
                      const float* __restrict__ shift, float* __restrict__ nms_sum) {
    const int HW = 196;
    int total = NB * 4 * HW;
    float local = 0.f;
    for (int idx = blockIdx.x * blockDim.x + threadIdx.x; idx < total;
         idx += gridDim.x * blockDim.x) {
        int p = idx % HW; int t = idx / HW;
        int c1 = t % 4; int b = t / 4;
        const float* base = x + ((size_t)b * 32 + c1 * 8) * HW + p;
        float v[8]; float m = -1e30f;
        #pragma unroll
        for (int j = 0; j < 8; j++) {
            int c = c1 * 8 + j;
            float u = fmaxf(0.f, fmaf(base[j * HW], scale[c], shift[c]));
            v[j] = u; if (u > m) m = u;
        }
        float s = 0.f;
        #pragma unroll
        for (int j = 0; j < 8; j++) if (v[j] != m) s += v[j];
        local += s;
    }
    local = warp_sum(local);
    __shared__ float sh[8];
    int lane = threadIdx.x & 31, wid = threadIdx.x >> 5;
    if (lane == 0) sh[wid] = local;
    __syncthreads();
    if (threadIdx.x == 0) {
        float a = 0.f;
        #pragma unroll
        for (int i = 0; i < 8; i++) a += sh[i];
        atomicAdd(nms_sum, a);
    }
}

// ---------------- conv7 + bias + global maxpool + NMS scalar ----------------
__global__ __launch_bounds__(256)
void k_conv7(const float* __restrict__ in, const float* __restrict__ w7,
             const float* __restrict__ b7, const float* __restrict__ nms_sum,
             float* __restrict__ out, int out_size) {
    __shared__ float s_in[64 * 16];
    __shared__ float s_w[10 * 64 * 16];
    __shared__ float s_res[250];
    __shared__ float s_b[10];
    int b = blockIdx.x, tid = threadIdx.x;
    for (int i = tid; i < 64 * 16; i += 256) s_in[i] = in[(size_t)b * 64 * 16 + i];
    for (int i = tid; i < 10 * 64 * 16; i += 256) s_w[i] = w7[i];
    if (tid < 10) s_b[tid] = b7[tid];
    __syncthreads();

    for (int item = tid; item < 250; item += 256) {
        int oc = item / 25; int pix = item % 25;
        int oy = pix / 5, ox = pix % 5;
        float a = 0.f;
        for (int ic = 0; ic < 64; ic++) {
            const float* ip = s_in + ic * 16;
            const float* wp = s_w + (oc * 64 + ic) * 16;
            #pragma unroll
            for (int ky = 0; ky < 4; ky++) {
                int iy = oy + ky - 2; if (iy < 0 || iy > 3) continue;
                #pragma unroll
                for (int kx = 0; kx < 4; kx++) {
                    int ix = ox + kx - 2; if (ix < 0 || ix > 3) continue;
                    a = fmaf(ip[iy * 4 + ix], wp[ky * 4 + kx], a);
                }
            }
        }
        s_res[item] = a;
    }
    __syncthreads();
    if (tid < 10) {
        float m = -1e30f;
        #pragma unroll
        for (int p = 0; p < 25; p++) m = fmaxf(m, s_res[tid * 25 + p]);
        out[b * 10 + tid] = m + s_b[tid];
    }
    if (b == 0 && tid == 0)
        out[out_size - 1] = nms_sum[0] * (1.0f / 12845056.0f);
}

// ---------------- launch ----------------
extern "C" void kernel_launch(void* const* d_in, const int* in_sizes, int n_in,
                              void* d_out, int out_size) {
    const float* x   = (const float*)d_in[0];
    const float* w1  = (const float*)d_in[1];
    const float* w2  = (const float*)d_in[2];
    const float* w3  = (const float*)d_in[3];
    const float* w4  = (const float*)d_in[4];
    const float* w5  = (const float*)d_in[5];
    const float* w6  = (const float*)d_in[6];
    const float* w7  = (const float*)d_in[7];
    const float* g1  = (const float*)d_in[8];
    const float* b1  = (const float*)d_in[9];
    const float* g2  = (const float*)d_in[10];
    const float* b2  = (const float*)d_in[11];
    const float* g3  = (const float*)d_in[12];
    const float* b3  = (const float*)d_in[13];
    const float* g4  = (const float*)d_in[14];
    const float* b4  = (const float*)d_in[15];
    const float* g5  = (const float*)d_in[16];
    const float* b5  = (const float*)d_in[17];
    const float* g6  = (const float*)d_in[18];
    const float* b6  = (const float*)d_in[19];
    const float* b7  = (const float*)d_in[20];
    float* out = (float*)d_out;

    float *buf1, *buf2, *buf3, *buf4, *buf5, *buf6, *buf7, *buf8, *buf9;
    float *rk1, *rk2, *rk3, *psum, *psumsq, *pscale, *pshift, *pnms;
    int* pcnt;
    cudaGetSymbolAddress((void**)&buf1, g_buf1);
    cudaGetSymbolAddress((void**)&buf2, g_buf2);
    cudaGetSymbolAddress((void**)&buf3, g_buf3);
    cudaGetSymbolAddress((void**)&buf4, g_buf4);
    cudaGetSymbolAddress((void**)&buf5, g_buf5);
    cudaGetSymbolAddress((void**)&buf6, g_buf6);
    cudaGetSymbolAddress((void**)&buf7, g_buf7);
    cudaGetSymbolAddress((void**)&buf8, g_buf8);
    cudaGetSymbolAddress((void**)&buf9, g_buf9);
    cudaGetSymbolAddress((void**)&rk1, g_rk1);
    cudaGetSymbolAddress((void**)&rk2, g_rk2);
    cudaGetSymbolAddress((void**)&rk3, g_rk3);
    cudaGetSymbolAddress((void**)&psum, g_sum);
    cudaGetSymbolAddress((void**)&psumsq, g_sumsq);
    cudaGetSymbolAddress((void**)&pscale, g_scale);
    cudaGetSymbolAddress((void**)&pshift, g_shift);
    cudaGetSymbolAddress((void**)&pcnt, g_cnt);
    cudaGetSymbolAddress((void**)&pnms, g_nms);

    // smem bytes: (IMGS*IMG_STRIDE + CIN*COUT*9) * 4
    const int SM1 = (1*(1*30*31+0)   + 1*16*9)  * 4;
    const int SM2 = (1*(16*30*31+0)  + 16*16*9) * 4;   //  68736
    const int SM3 = (1*(16*16*19+0)  + 16*32*9) * 4;   //  37888
    const int SM4 = (1*(32*16*19+0)  + 32*32*9) * 4;   //  75776
    const int SM5 = (2*(32*9*11+8)   + 32*64*9) * 4;   //  99136
    const int SM6 = (2*(64*9*11+8)   + 64*64*9) * 4;   // 198208

    cudaFuncSetAttribute(conv3x3v3<16,16,28,28,1,31,0,true>,  cudaFuncAttributeMaxDynamicSharedMemorySize, SM2);
    cudaFuncSetAttribute(conv3x3v3<32,32,14,14,1,19,0,true>,  cudaFuncAttributeMaxDynamicSharedMemorySize, SM4);
    cudaFuncSetAttribute(conv3x3v3<32,64,7,7,2,11,8,false>,   cudaFuncAttributeMaxDynamicSharedMemorySize, SM5);
    cudaFuncSetAttribute(conv3x3v3<64,64,7,7,2,11,8,true>,    cudaFuncAttributeMaxDynamicSharedMemorySize, SM6);

    const float invN784 = 1.0f / (2048.0f * 784.0f);
    const float invN196 = 1.0f / (2048.0f * 196.0f);
    const float invN49  = 1.0f / (2048.0f * 49.0f);

    k_build_rk<<<4, 256>>>(w1, w2, w3);

    conv3x3v3<1,16,28,28,1,31,0,false><<<NB, 224, SM1>>>(x, rk1, nullptr, nullptr, buf1);
    k_statsfin4<<<dim3(64, 16), 256>>>(buf1, psum + ST1, psumsq + ST1, pcnt + ST1,
                                       g1, b1, pscale + ST1, pshift + ST1, 16, 196, 2, invN784);
    // launch 3 (PROFILED): conv2
    conv3x3v3<16,16,28,28,1,31,0,true><<<NB, 224, SM2>>>(buf1, rk2, pscale + ST1, pshift + ST1, buf2);
    k_statsfin4<<<dim3(64, 16), 256>>>(buf2, psum + ST2, psumsq + ST2, pcnt + ST2,
                                       g2, b2, pscale + ST2, pshift + ST2, 16, 196, 2, invN784);

    k_pool<16,28,28,0><<<4096, 256>>>(buf2, pscale + ST2, pshift + ST2, buf3);

    conv3x3v3<16,32,14,14,1,19,0,false><<<NB, 224, SM3>>>(buf3, rk3, nullptr, nullptr, buf4);
    k_statsfin4<<<dim3(64, 32), 256>>>(buf4, psum + ST3, psumsq + ST3, pcnt + ST3,
                                       g3, b3, pscale + ST3, pshift + ST3, 32, 49, 4, invN196);

    k_nms<<<1024, 256>>>(buf4, pscale + ST3, pshift + ST3, pnms);

    conv3x3v3<32,32,14,14,1,19,0,true><<<NB, 224, SM4>>>(buf4, w4, pscale + ST3, pshift + ST3, buf5);
    k_statsfin4<<<dim3(64, 32), 256>>>(buf5, psum + ST4, psumsq + ST4, pcnt + ST4,
                                       g4, b4, pscale + ST4, pshift + ST4, 32, 49, 32, invN196);

    k_pool<32,14,14,0><<<2048, 256>>>(buf5, pscale + ST4, pshift + ST4, buf6);

    conv3x3v3<32,64,7,7,2,11,8,false><<<NB/2, 224, SM5>>>(buf6, w5, nullptr, nullptr, buf7);
    k_statsfin<<<dim3(64, 64), 256>>>(buf7, psum + ST5, psumsq + ST5, pcnt + ST5,
                                      g5, b5, pscale + ST5, pshift + ST5, 64, 49, 64, invN49);

    conv3x3v3<64,64,7,7,2,11,8,true><<<NB/2, 224, SM6>>>(buf7, w6, pscale + ST5, pshift + ST5, buf8);
    k_statsfin<<<dim3(64, 64), 256>>>(buf8, psum + ST6, psumsq + ST6, pcnt + ST6,
                                      g6, b6, pscale + ST6, pshift + ST6, 64, 49, 64, invN49);

    k_pool<64,7,7,1><<<1024, 256>>>(buf8, pscale + ST6, pshift + ST6, buf9);

    k_conv7<<<NB, 256>>>(buf9, w7, b7, pnms, out, out_size);
}

// round 5
// speedup vs baseline: 1.5488x; 1.5488x over previous
#include <cuda_runtime.h>
#include <math.h>

#define NB 2048

typedef unsigned long long u64;

// ---------------- scratch ----------------
__device__ float g_buf1[NB*16*28*28];
__device__ float g_buf2[NB*16*28*28];
__device__ float g_buf3[NB*16*14*14];
__device__ float g_buf4[NB*32*14*14];
__device__ float g_buf5[NB*32*14*14];
__device__ float g_buf6[NB*32*7*7];
__device__ float g_buf7[NB*64*7*7];
__device__ float g_buf8[NB*64*7*7];
__device__ float g_buf9[NB*64*4*4];
__device__ float g_rk1[16*1*9];
__device__ float g_rk2[16*16*9];
__device__ float g_rk3[32*16*9];
__device__ float g_sum[224];
__device__ float g_sumsq[224];
__device__ float g_scale[224];
__device__ float g_shift[224];
__device__ int   g_cnt[224];
__device__ float g_nms;

#define ST1 0
#define ST2 16
#define ST3 32
#define ST4 64
#define ST5 96
#define ST6 160

// ---------------- packed fp32x2 helpers ----------------
__device__ __forceinline__ u64 pack2(float lo, float hi) {
    u64 r; asm("mov.b64 %0, {%1, %2};" : "=l"(r) : "f"(lo), "f"(hi)); return r;
}
__device__ __forceinline__ u64 fma2(u64 a, u64 b, u64 c) {
    u64 d; asm("fma.rn.f32x2 %0, %1, %2, %3;" : "=l"(d) : "l"(a), "l"(b), "l"(c)); return d;
}
__device__ __forceinline__ void unpack2(u64 v, float& lo, float& hi) {
    asm("mov.b64 {%0, %1}, %2;" : "=f"(lo), "=f"(hi) : "l"(v));
}

__device__ __forceinline__ float warp_sum(float v) {
    #pragma unroll
    for (int o = 16; o > 0; o >>= 1) v += __shfl_xor_sync(0xffffffffu, v, o);
    return v;
}

// ---------------- build rotated kernels + zero accumulators ----------------
__global__ void k_build_rk(const float* __restrict__ w1, const float* __restrict__ w2,
                           const float* __restrict__ w3) {
    int idx = blockIdx.x * blockDim.x + threadIdx.x;
    if (idx < 224) { g_sum[idx] = 0.f; g_sumsq[idx] = 0.f; g_cnt[idx] = 0; }
    if (idx == 0) g_nms = 0.f;
    if (idx >= 16 + 256 + 512) return;
    float local[9];
    #pragma unroll
    for (int k = 0; k < 9; k++) local[k] = 0.f;

    int i, a, ic = 0, which;
    if (idx < 16)       { which = 0; i = idx >> 1; a = idx & 1; }
    else if (idx < 272) { int e = idx - 16;  which = 1; ic = e & 15; a = (e >> 4) & 1; i = e >> 5; }
    else                { int e = idx - 272; which = 2; ic = e & 15; a = (e >> 4) & 3; i = e >> 6; }

    double th = 0.78539816339744831 * (double)i;
    double ct = cos(th), st = sin(th);

    int ics = ic;
    if (which != 0) {
        int bnew = ic >> 1, sub = ic & 1;
        int bsrc = ((bnew - i) % 8 + 8) % 8;
        ics = bsrc * 2 + sub;
    }
    const float* src;
    if (which == 0)      src = w1 + a * 9;
    else if (which == 1) src = w2 + (a * 16 + ics) * 9;
    else                 src = w3 + (a * 16 + ics) * 9;

    #pragma unroll
    for (int t = 0; t < 9; t++) {
        int row = t / 3, col = t % 3;
        double x = (double)(col - 1), y = (double)(row - 1);
        int xr = (int)llrint(x * ct + y * st);
        int yr = (int)llrint(-x * st + y * ct);
        local[(1 - yr) * 3 + (1 - xr)] += src[t];
    }

    float* dst;
    if (which == 0)      dst = g_rk1 + (i * 2 + a) * 9;
    else if (which == 1) dst = g_rk2 + ((i * 2 + a) * 16 + ic) * 9;
    else                 dst = g_rk3 + ((i * 4 + a) * 16 + ic) * 9;
    #pragma unroll
    for (int k = 0; k < 9; k++) dst[k] = local[k];
}

// ---------------- conv3x3, lane->gy mapping, odd WPAD (conflict-free LDS) ----------
template<int CIN, int COUT, int H, int W, int IMGS, int WPAD, int IMG_PAD, bool BN_IN>
__global__ __launch_bounds__(224, 3)
void conv3x3v3(const float* __restrict__ in, const float* __restrict__ wt,
               const float* __restrict__ scale, const float* __restrict__ shift,
               float* __restrict__ out) {
    constexpr int G = (W + 3) / 4;
    constexpr int HP = H + 2;
    constexpr int PLANE = HP * WPAD;
    constexpr int IMG_STRIDE = CIN * PLANE + IMG_PAD;
    constexpr int OCG = COUT / 8;
    constexpr int ITEMS = IMGS * OCG * G * H;
    constexpr int P = H * W;
    constexpr int WFLOATS = CIN * COUT * 9;

    extern __shared__ float sm[];
    float* s_in = sm;                        // IMGS * IMG_STRIDE
    float* s_w  = sm + IMGS * IMG_STRIDE;    // [ic][oc/2][9] float2 pairs

    const int b0 = blockIdx.x * IMGS;
    const int tid = threadIdx.x;

    for (int idx = tid; idx < WFLOATS; idx += 224) {
        int h = idx & 1; int u = idx >> 1;
        int t = u % 9; u /= 9;
        int op = u % (COUT / 2); int ic = u / (COUT / 2);
        s_w[idx] = wt[((2 * op + h) * CIN + ic) * 9 + t];
    }
    for (int idx = tid; idx < IMGS * CIN * HP * WPAD; idx += 224) {
        int c = idx % WPAD; int t = idx / WPAD;
        int r = t % HP; t /= HP;
        int ic = t % CIN; int img = t / CIN;
        float v = 0.f;
        if (r >= 1 && r <= H && c >= 1 && c <= W) {
            v = in[(((size_t)(b0 + img) * CIN + ic) * H + (r - 1)) * W + (c - 1)];
            if (BN_IN) v = fmaxf(0.f, fmaf(v, scale[ic], shift[ic]));
        }
        s_in[img * IMG_STRIDE + ic * PLANE + r * WPAD + c] = v;
    }
    __syncthreads();

    const u64* w64 = (const u64*)s_w;

    for (int item = tid; item < ITEMS; item += 224) {
        int gy = item % H; int t = item / H;
        int gx = t % G; t /= G;
        int img = t % IMGS; int ocg = t / IMGS;

        u64 acc[4][4];
        #pragma unroll
        for (int px = 0; px < 4; px++)
            #pragma unroll
            for (int op = 0; op < 4; op++) acc[px][op] = 0ull;

        const float* ibase = s_in + img * IMG_STRIDE + gy * WPAD + 4 * gx;
        const u64* wbase = w64 + (size_t)ocg * 4 * 9;

        #pragma unroll 2
        for (int ic = 0; ic < CIN; ic++) {
            const float* ip = ibase + ic * PLANE;
            const u64* wrow = wbase + (size_t)ic * (COUT / 2) * 9;
            #pragma unroll
            for (int r = 0; r < 3; r++) {
                float i0 = ip[r * WPAD + 0], i1 = ip[r * WPAD + 1], i2 = ip[r * WPAD + 2];
                float i3 = ip[r * WPAD + 3], i4 = ip[r * WPAD + 4], i5 = ip[r * WPAD + 5];
                u64 d0 = pack2(i0, i0), d1 = pack2(i1, i1), d2 = pack2(i2, i2);
                u64 d3 = pack2(i3, i3), d4 = pack2(i4, i4), d5 = pack2(i5, i5);
                #pragma unroll
                for (int op = 0; op < 4; op++) {
                    const u64* w9 = wrow + op * 9 + r * 3;
                    u64 w;
                    w = w9[0];
                    acc[0][op] = fma2(d0, w, acc[0][op]);
                    acc[1][op] = fma2(d1, w, acc[1][op]);
                    acc[2][op] = fma2(d2, w, acc[2][op]);
                    acc[3][op] = fma2(d3, w, acc[3][op]);
                    w = w9[1];
                    acc[0][op] = fma2(d1, w, acc[0][op]);
                    acc[1][op] = fma2(d2, w, acc[1][op]);
                    acc[2][op] = fma2(d3, w, acc[2][op]);
                    acc[3][op] = fma2(d4, w, acc[3][op]);
                    w = w9[2];
                    acc[0][op] = fma2(d2, w, acc[0][op]);
                    acc[1][op] = fma2(d3, w, acc[1][op]);
                    acc[2][op] = fma2(d4, w, acc[2][op]);
                    acc[3][op] = fma2(d5, w, acc[3][op]);
                }
            }
        }

        float* outb = out + ((size_t)(b0 + img) * COUT + ocg * 8) * P + gy * W + 4 * gx;
        if (W % 4 == 0) {
            #pragma unroll
            for (int op = 0; op < 4; op++) {
                float l0, h0, l1, h1, l2, h2, l3, h3;
                unpack2(acc[0][op], l0, h0); unpack2(acc[1][op], l1, h1);
                unpack2(acc[2][op], l2, h2); unpack2(acc[3][op], l3, h3);
                *(float4*)(outb + (2 * op) * P)     = make_float4(l0, l1, l2, l3);
                *(float4*)(outb + (2 * op + 1) * P) = make_float4(h0, h1, h2, h3);
            }
        } else if (W % 2 == 0) {
            #pragma unroll
            for (int op = 0; op < 4; op++) {
                float l0, h0, l1, h1, l2, h2, l3, h3;
                unpack2(acc[0][op], l0, h0); unpack2(acc[1][op], l1, h1);
                unpack2(acc[2][op], l2, h2); unpack2(acc[3][op], l3, h3);
                *(float2*)(outb + (2 * op) * P)     = make_float2(l0, l1);
                *(float2*)(outb + (2 * op + 1) * P) = make_float2(h0, h1);
                if (4 * gx + 3 < W) {
                    *(float2*)(outb + (2 * op) * P + 2)     = make_float2(l2, l3);
                    *(float2*)(outb + (2 * op + 1) * P + 2) = make_float2(h2, h3);
                }
            }
        } else {
            int nvalid = W - 4 * gx; if (nvalid > 4) nvalid = 4;
            #pragma unroll
            for (int op = 0; op < 4; op++) {
                #pragma unroll
                for (int px = 0; px < 4; px++) {
                    if (px < nvalid) {
                        float lo, hi;
                        unpack2(acc[px][op], lo, hi);
                        outb[(2 * op) * P + px]     = lo;
                        outb[(2 * op + 1) * P + px] = hi;
                    }
                }
            }
        }
    }
}

// ---------------- stats + last-block finalize ----------------
__global__ void k_statsfin4(const float* __restrict__ x, float* __restrict__ sum,
                            float* __restrict__ sumsq, int* __restrict__ cnt,
                            const float* __restrict__ gamma, const float* __restrict__ beta,
                            float* __restrict__ scale, float* __restrict__ shift,
                            int C, int HW4, int gmod, float invN) {
    int c = blockIdx.y;
    float s = 0.f, s2 = 0.f;
    int N4 = NB * HW4;
    const float4* xp = (const float4*)x;
    for (int idx = blockIdx.x * blockDim.x + threadIdx.x; idx < N4;
         idx += gridDim.x * blockDim.x) {
        int b = idx / HW4; int p = idx - b * HW4;
        float4 v = xp[(size_t)(b * C + c) * HW4 + p];
        s += (v.x + v.y) + (v.z + v.w);
        s2 = fmaf(v.x, v.x, s2); s2 = fmaf(v.y, v.y, s2);
        s2 = fmaf(v.z, v.z, s2); s2 = fmaf(v.w, v.w, s2);
    }
    s = warp_sum(s); s2 = warp_sum(s2);
    __shared__ float sh[2][8];
    int lane = threadIdx.x & 31, wid = threadIdx.x >> 5;
    if (lane == 0) { sh[0][wid] = s; sh[1][wid] = s2; }
    __syncthreads();
    if (threadIdx.x == 0) {
        float a = 0.f, b2 = 0.f;
        #pragma unroll
        for (int i = 0; i < 8; i++) { a += sh[0][i]; b2 += sh[1][i]; }
        atomicAdd(&sum[c], a); atomicAdd(&sumsq[c], b2);
        __threadfence();
        int t = atomicAdd(&cnt[c], 1);
        if (t == (int)gridDim.x - 1) {
            __threadfence();
            float Ssum = *((volatile float*)&sum[c]);
            float Ssq  = *((volatile float*)&sumsq[c]);
            float mean = Ssum * invN;
            float var  = Ssq * invN - mean * mean;
            float sc = gamma[c % gmod] * rsqrtf(var + 1e-5f);
            scale[c] = sc;
            shift[c] = beta[c % gmod] - mean * sc;
        }
    }
}

__global__ void k_statsfin(const float* __restrict__ x, float* __restrict__ sum,
                           float* __restrict__ sumsq, int* __restrict__ cnt,
                           const float* __restrict__ gamma, const float* __restrict__ beta,
                           float* __restrict__ scale, float* __restrict__ shift,
                           int C, int HW, int gmod, float invN) {
    int c = blockIdx.y;
    float s = 0.f, s2 = 0.f;
    int N = NB * HW;
    for (int idx = blockIdx.x * blockDim.x + threadIdx.x; idx < N;
         idx += gridDim.x * blockDim.x) {
        int b = idx / HW; int p = idx - b * HW;
        float v = x[((size_t)b * C + c) * HW + p];
        s += v; s2 = fmaf(v, v, s2);
    }
    s = warp_sum(s); s2 = warp_sum(s2);
    __shared__ float sh[2][8];
    int lane = threadIdx.x & 31, wid = threadIdx.x >> 5;
    if (lane == 0) { sh[0][wid] = s; sh[1][wid] = s2; }
    __syncthreads();
    if (threadIdx.x == 0) {
        float a = 0.f, b2 = 0.f;
        #pragma unroll
        for (int i = 0; i < 8; i++) { a += sh[0][i]; b2 += sh[1][i]; }
        atomicAdd(&sum[c], a); atomicAdd(&sumsq[c], b2);
        __threadfence();
        int t = atomicAdd(&cnt[c], 1);
        if (t == (int)gridDim.x - 1) {
            __threadfence();
            float Ssum = *((volatile float*)&sum[c]);
            float Ssq  = *((volatile float*)&sumsq[c]);
            float mean = Ssum * invN;
            float var  = Ssq * invN - mean * mean;
            float sc = gamma[c % gmod] * rsqrtf(var + 1e-5f);
            scale[c] = sc;
            shift[c] = beta[c % gmod] - mean * sc;
        }
    }
}

// ---------------- BN + ReLU + 2x2 maxpool ----------------
template<int C, int H, int W, int PAD>
__global__ void k_pool(const float* __restrict__ in, const float* __restrict__ scale,
                       const float* __restrict__ shift, float* __restrict__ out) {
    constexpr int HO = (H + 2 * PAD) / 2, WO = (W + 2 * PAD) / 2;
    int total = NB * C * HO * WO;
    for (int idx = blockIdx.x * blockDim.x + threadIdx.x; idx < total;
         idx += gridDim.x * blockDim.x) {
        int wo = idx % WO; int t = idx / WO;
        int ho = t % HO; t /= HO;
        int c = t % C; int b = t / C;
        const float* p = in + ((size_t)b * C + c) * (H * W);
        float sc = scale[c], sh = shift[c];
        float m = -1e30f;
        int iy0 = ho * 2 - PAD, ix0 = wo * 2 - PAD;
        #pragma unroll
        for (int dy = 0; dy < 2; dy++) {
            int iy = iy0 + dy; if (iy < 0 || iy >= H) continue;
            #pragma unroll
            for (int dx = 0; dx < 2; dx++) {
                int ix = ix0 + dx; if (ix < 0 || ix >= W) continue;
                float v = fmaxf(0.f, fmaf(p[iy * W + ix], sc, sh));
                if (v > m) m = v;
            }
        }
        out[idx] = m;
    }
}

// ---------------- NMS (rotation-minor channel view c = c1*8 + j) ----------------
__global__ void k_nms(const float* __restrict__ x, const float* __restrict__ scale,
                      const float* __restrict__ shift, float* __restrict__ nms_sum) {
    const int HW = 196;
    int total = NB * 4 * HW;
    float local = 0.f;
    for (int idx = blockIdx.x * blockDim.x + threadIdx.x; idx < total;
         idx += gridDim.x * blockDim.x) {
        int p = idx % HW; int t = idx / HW;
        int c1 = t % 4; int b = t / 4;
        const float* base = x + ((size_t)b * 32 + c1 * 8) * HW + p;
        float v[8]; float m = -1e30f;
        #pragma unroll
        for (int j = 0; j < 8; j++) {
            int c = c1 * 8 + j;
            float u = fmaxf(0.f, fmaf(base[j * HW], scale[c], shift[c]));
            v[j] = u; if (u > m) m = u;
        }
        float s = 0.f;
        #pragma unroll
        for (int j = 0; j < 8; j++) if (v[j] != m) s += v[j];
        local += s;
    }
    local = warp_sum(local);
    __shared__ float sh[8];
    int lane = threadIdx.x & 31, wid = threadIdx.x >> 5;
    if (lane == 0) sh[wid] = local;
    __syncthreads();
    if (threadIdx.x == 0) {
        float a = 0.f;
        #pragma unroll
        for (int i = 0; i < 8; i++) a += sh[i];
        atomicAdd(nms_sum, a);
    }
}

// ---------------- conv7 + bias + global maxpool + NMS scalar ----------------
__global__ __launch_bounds__(256)
void k_conv7(const float* __restrict__ in, const float* __restrict__ w7,
             const float* __restrict__ b7, const float* __restrict__ nms_sum,
             float* __restrict__ out, int out_size) {
    __shared__ float s_in[64 * 16];
    __shared__ float s_w[10 * 64 * 16];
    __shared__ float s_res[250];
    __shared__ float s_b[10];
    int b = blockIdx.x, tid = threadIdx.x;
    for (int i = tid; i < 64 * 16; i += 256) s_in[i] = in[(size_t)b * 64 * 16 + i];
    for (int i = tid; i < 10 * 64 * 16; i += 256) s_w[i] = w7[i];
    if (tid < 10) s_b[tid] = b7[tid];
    __syncthreads();

    for (int item = tid; item < 250; item += 256) {
        int oc = item / 25; int pix = item % 25;
        int oy = pix / 5, ox = pix % 5;
        float a = 0.f;
        for (int ic = 0; ic < 64; ic++) {
            const float* ip = s_in + ic * 16;
            const float* wp = s_w + (oc * 64 + ic) * 16;
            #pragma unroll
            for (int ky = 0; ky < 4; ky++) {
                int iy = oy + ky - 2; if (iy < 0 || iy > 3) continue;
                #pragma unroll
                for (int kx = 0; kx < 4; kx++) {
                    int ix = ox + kx - 2; if (ix < 0 || ix > 3) continue;
                    a = fmaf(ip[iy * 4 + ix], wp[ky * 4 + kx], a);
                }
            }
        }
        s_res[item] = a;
    }
    __syncthreads();
    if (tid < 10) {
        float m = -1e30f;
        #pragma unroll
        for (int p = 0; p < 25; p++) m = fmaxf(m, s_res[tid * 25 + p]);
        out[b * 10 + tid] = m + s_b[tid];
    }
    if (b == 0 && tid == 0)
        out[out_size - 1] = nms_sum[0] * (1.0f / 12845056.0f);
}

// ---------------- launch ----------------
extern "C" void kernel_launch(void* const* d_in, const int* in_sizes, int n_in,
                              void* d_out, int out_size) {
    const float* x   = (const float*)d_in[0];
    const float* w1  = (const float*)d_in[1];
    const float* w2  = (const float*)d_in[2];
    const float* w3  = (const float*)d_in[3];
    const float* w4  = (const float*)d_in[4];
    const float* w5  = (const float*)d_in[5];
    const float* w6  = (const float*)d_in[6];
    const float* w7  = (const float*)d_in[7];
    const float* g1  = (const float*)d_in[8];
    const float* b1  = (const float*)d_in[9];
    const float* g2  = (const float*)d_in[10];
    const float* b2  = (const float*)d_in[11];
    const float* g3  = (const float*)d_in[12];
    const float* b3  = (const float*)d_in[13];
    const float* g4  = (const float*)d_in[14];
    const float* b4  = (const float*)d_in[15];
    const float* g5  = (const float*)d_in[16];
    const float* b5  = (const float*)d_in[17];
    const float* g6  = (const float*)d_in[18];
    const float* b6  = (const float*)d_in[19];
    const float* b7  = (const float*)d_in[20];
    float* out = (float*)d_out;

    float *buf1, *buf2, *buf3, *buf4, *buf5, *buf6, *buf7, *buf8, *buf9;
    float *rk1, *rk2, *rk3, *psum, *psumsq, *pscale, *pshift, *pnms;
    int* pcnt;
    cudaGetSymbolAddress((void**)&buf1, g_buf1);
    cudaGetSymbolAddress((void**)&buf2, g_buf2);
    cudaGetSymbolAddress((void**)&buf3, g_buf3);
    cudaGetSymbolAddress((void**)&buf4, g_buf4);
    cudaGetSymbolAddress((void**)&buf5, g_buf5);
    cudaGetSymbolAddress((void**)&buf6, g_buf6);
    cudaGetSymbolAddress((void**)&buf7, g_buf7);
    cudaGetSymbolAddress((void**)&buf8, g_buf8);
    cudaGetSymbolAddress((void**)&buf9, g_buf9);
    cudaGetSymbolAddress((void**)&rk1, g_rk1);
    cudaGetSymbolAddress((void**)&rk2, g_rk2);
    cudaGetSymbolAddress((void**)&rk3, g_rk3);
    cudaGetSymbolAddress((void**)&psum, g_sum);
    cudaGetSymbolAddress((void**)&psumsq, g_sumsq);
    cudaGetSymbolAddress((void**)&pscale, g_scale);
    cudaGetSymbolAddress((void**)&pshift, g_shift);
    cudaGetSymbolAddress((void**)&pcnt, g_cnt);
    cudaGetSymbolAddress((void**)&pnms, g_nms);

    // smem bytes: (IMGS*IMG_STRIDE + CIN*COUT*9) * 4
    const int SM1 = (1*(1*30*31+0)   + 1*16*9)  * 4;
    const int SM2 = (1*(16*30*31+0)  + 16*16*9) * 4;   //  68736
    const int SM3 = (1*(16*16*19+0)  + 16*32*9) * 4;   //  37888
    const int SM4 = (1*(32*16*19+0)  + 32*32*9) * 4;   //  75776
    const int SM5 = (2*(32*9*11+8)   + 32*64*9) * 4;   //  99136
    const int SM6 = (2*(64*9*11+8)   + 64*64*9) * 4;   // 198208

    cudaFuncSetAttribute(conv3x3v3<16,16,28,28,1,31,0,true>,  cudaFuncAttributeMaxDynamicSharedMemorySize, SM2);
    cudaFuncSetAttribute(conv3x3v3<32,32,14,14,1,19,0,true>,  cudaFuncAttributeMaxDynamicSharedMemorySize, SM4);
    cudaFuncSetAttribute(conv3x3v3<32,64,7,7,2,11,8,false>,   cudaFuncAttributeMaxDynamicSharedMemorySize, SM5);
    cudaFuncSetAttribute(conv3x3v3<64,64,7,7,2,11,8,true>,    cudaFuncAttributeMaxDynamicSharedMemorySize, SM6);

    const float invN784 = 1.0f / (2048.0f * 784.0f);
    const float invN196 = 1.0f / (2048.0f * 196.0f);
    const float invN49  = 1.0f / (2048.0f * 49.0f);

    k_build_rk<<<4, 256>>>(w1, w2, w3);

    conv3x3v3<1,16,28,28,1,31,0,false><<<NB, 224, SM1>>>(x, rk1, nullptr, nullptr, buf1);
    k_statsfin4<<<dim3(64, 16), 256>>>(buf1, psum + ST1, psumsq + ST1, pcnt + ST1,
                                       g1, b1, pscale + ST1, pshift + ST1, 16, 196, 2, invN784);
    // launch 3 (PROFILED): conv2
    conv3x3v3<16,16,28,28,1,31,0,true><<<NB, 224, SM2>>>(buf1, rk2, pscale + ST1, pshift + ST1, buf2);
    k_statsfin4<<<dim3(64, 16), 256>>>(buf2, psum + ST2, psumsq + ST2, pcnt + ST2,
                                       g2, b2, pscale + ST2, pshift + ST2, 16, 196, 2, invN784);

    k_pool<16,28,28,0><<<4096, 256>>>(buf2, pscale + ST2, pshift + ST2, buf3);

    conv3x3v3<16,32,14,14,1,19,0,false><<<NB, 224, SM3>>>(buf3, rk3, nullptr, nullptr, buf4);
    k_statsfin4<<<dim3(64, 32), 256>>>(buf4, psum + ST3, psumsq + ST3, pcnt + ST3,
                                       g3, b3, pscale + ST3, pshift + ST3, 32, 49, 4, invN196);

    k_nms<<<1024, 256>>>(buf4, pscale + ST3, pshift + ST3, pnms);

    conv3x3v3<32,32,14,14,1,19,0,true><<<NB, 224, SM4>>>(buf4, w4, pscale + ST3, pshift + ST3, buf5);
    k_statsfin4<<<dim3(64, 32), 256>>>(buf5, psum + ST4, psumsq + ST4, pcnt + ST4,
                                       g4, b4, pscale + ST4, pshift + ST4, 32, 49, 32, invN196);

    k_pool<32,14,14,0><<<2048, 256>>>(buf5, pscale + ST4, pshift + ST4, buf6);

    conv3x3v3<32,64,7,7,2,11,8,false><<<NB/2, 224, SM5>>>(buf6, w5, nullptr, nullptr, buf7);
    k_statsfin<<<dim3(64, 64), 256>>>(buf7, psum + ST5, psumsq + ST5, pcnt + ST5,
                                      g5, b5, pscale + ST5, pshift + ST5, 64, 49, 64, invN49);

    conv3x3v3<64,64,7,7,2,11,8,true><<<NB/2, 224, SM6>>>(buf7, w6, pscale + ST5, pshift + ST5, buf8);
    k_statsfin<<<dim3(64, 64), 256>>>(buf8, psum + ST6, psumsq + ST6, pcnt + ST6,
                                      g6, b6, pscale + ST6, pshift + ST6, 64, 49, 64, invN49);

    k_pool<64,7,7,1><<<1024, 256>>>(buf8, pscale + ST6, pshift + ST6, buf9);

    k_conv7<<<NB, 256>>>(buf9, w7, b7, pnms, out, out_size);
}

// round 6
// speedup vs baseline: 1.7452x; 1.1268x over previous
#include <cuda_runtime.h>
#include <math.h>

#define NB 2048

typedef unsigned long long u64;

// ---------------- scratch ----------------
__device__ float g_buf1[NB*16*28*28];
__device__ float g_buf2[NB*16*28*28];
__device__ float g_buf3[NB*16*14*14];
__device__ float g_buf4[NB*32*14*14];
__device__ float g_buf5[NB*32*14*14];
__device__ float g_buf6[NB*32*7*7];
__device__ float g_buf7[NB*64*7*7];
__device__ float g_buf8[NB*64*7*7];
__device__ float g_buf9[NB*64*4*4];
__device__ float g_rk1[16*1*9];
__device__ float g_rk2[16*16*9];
__device__ float g_rk3[32*16*9];
__device__ float g_sum[224];
__device__ float g_sumsq[224];
__device__ float g_scale[224];
__device__ float g_shift[224];
__device__ int   g_cnt[224];
__device__ float g_nms;

#define ST1 0
#define ST2 16
#define ST3 32
#define ST4 64
#define ST5 96
#define ST6 160

// ---------------- packed fp32x2 helpers ----------------
__device__ __forceinline__ u64 pack2(float lo, float hi) {
    u64 r; asm("mov.b64 %0, {%1, %2};" : "=l"(r) : "f"(lo), "f"(hi)); return r;
}
__device__ __forceinline__ u64 fma2(u64 a, u64 b, u64 c) {
    u64 d; asm("fma.rn.f32x2 %0, %1, %2, %3;" : "=l"(d) : "l"(a), "l"(b), "l"(c)); return d;
}
__device__ __forceinline__ void unpack2(u64 v, float& lo, float& hi) {
    asm("mov.b64 {%0, %1}, %2;" : "=f"(lo), "=f"(hi) : "l"(v));
}

__device__ __forceinline__ float warp_sum(float v) {
    #pragma unroll
    for (int o = 16; o > 0; o >>= 1) v += __shfl_xor_sync(0xffffffffu, v, o);
    return v;
}

// ---------------- zero the split-K accumulation buffers (every replay) ------------
__global__ void k_zero_bufs() {
    size_t i = (size_t)blockIdx.x * blockDim.x + threadIdx.x;
    size_t stride = (size_t)gridDim.x * blockDim.x;
    float4 z = make_float4(0.f, 0.f, 0.f, 0.f);
    const size_t n5 = (size_t)NB*32*196/4, n7 = (size_t)NB*64*49/4;
    float4* p5 = (float4*)g_buf5; float4* p7 = (float4*)g_buf7; float4* p8 = (float4*)g_buf8;
    for (size_t j = i; j < n5; j += stride) p5[j] = z;
    for (size_t j = i; j < n7; j += stride) p7[j] = z;
    for (size_t j = i; j < n7; j += stride) p8[j] = z;
}

// ---------------- build rotated kernels + zero stat accumulators ----------------
__global__ void k_build_rk(const float* __restrict__ w1, const float* __restrict__ w2,
                           const float* __restrict__ w3) {
    int idx = blockIdx.x * blockDim.x + threadIdx.x;
    if (idx < 224) { g_sum[idx] = 0.f; g_sumsq[idx] = 0.f; g_cnt[idx] = 0; }
    if (idx == 0) g_nms = 0.f;
    if (idx >= 16 + 256 + 512) return;
    float local[9];
    #pragma unroll
    for (int k = 0; k < 9; k++) local[k] = 0.f;

    int i, a, ic = 0, which;
    if (idx < 16)       { which = 0; i = idx >> 1; a = idx & 1; }
    else if (idx < 272) { int e = idx - 16;  which = 1; ic = e & 15; a = (e >> 4) & 1; i = e >> 5; }
    else                { int e = idx - 272; which = 2; ic = e & 15; a = (e >> 4) & 3; i = e >> 6; }

    double th = 0.78539816339744831 * (double)i;
    double ct = cos(th), st = sin(th);

    int ics = ic;
    if (which != 0) {
        int bnew = ic >> 1, sub = ic & 1;
        int bsrc = ((bnew - i) % 8 + 8) % 8;
        ics = bsrc * 2 + sub;
    }
    const float* src;
    if (which == 0)      src = w1 + a * 9;
    else if (which == 1) src = w2 + (a * 16 + ics) * 9;
    else                 src = w3 + (a * 16 + ics) * 9;

    #pragma unroll
    for (int t = 0; t < 9; t++) {
        int row = t / 3, col = t % 3;
        double x = (double)(col - 1), y = (double)(row - 1);
        int xr = (int)llrint(x * ct + y * st);
        int yr = (int)llrint(-x * st + y * ct);
        local[(1 - yr) * 3 + (1 - xr)] += src[t];
    }

    float* dst;
    if (which == 0)      dst = g_rk1 + (i * 2 + a) * 9;
    else if (which == 1) dst = g_rk2 + ((i * 2 + a) * 16 + ic) * 9;
    else                 dst = g_rk3 + ((i * 4 + a) * 16 + ic) * 9;
    #pragma unroll
    for (int k = 0; k < 9; k++) dst[k] = local[k];
}

// ---------------- conv3x3 v4: row-section + input-channel split, high occupancy ----
// grid: (img_groups, H/HS, ICSPLIT). Item = 4 pixels x 8 oc (4 FMA2 oc-pairs).
// Lane->gy mapping + odd WPAD keeps LDS conflict-free. ACCUM layers atomicAdd
// partial (ic-slice) sums into a pre-zeroed buffer.
template<int CIN, int COUT, int H, int W, int HS, int IMGS, int WPAD, int IMG_PAD,
         int ICSPLIT, bool BN_IN, bool ACCUM>
__global__ __launch_bounds__(256, 4)
void conv3x3v4(const float* __restrict__ in, const float* __restrict__ wt,
               const float* __restrict__ scale, const float* __restrict__ shift,
               float* __restrict__ out) {
    constexpr int CINB = CIN / ICSPLIT;
    constexpr int G = (W + 3) / 4;
    constexpr int HPT = HS + 2;
    constexpr int PLANE = HPT * WPAD;
    constexpr int IMG_STRIDE = CINB * PLANE + IMG_PAD;
    constexpr int OCG = COUT / 8;
    constexpr int ITEMS = IMGS * OCG * G * HS;
    constexpr int P = H * W;
    constexpr int WFLOATS = CINB * COUT * 9;

    extern __shared__ float sm[];
    float* s_in = sm;                        // IMGS * IMG_STRIDE
    float* s_w  = sm + IMGS * IMG_STRIDE;    // [ic][oc/2][9] float2 pairs

    const int b0 = blockIdx.x * IMGS;
    const int row0 = blockIdx.y * HS;
    const int icz = blockIdx.z;
    const int tid = threadIdx.x;

    for (int idx = tid; idx < WFLOATS; idx += 256) {
        int h = idx & 1; int u = idx >> 1;
        int t = u % 9; u /= 9;
        int op = u % (COUT / 2); int ic = u / (COUT / 2);
        s_w[idx] = wt[((2 * op + h) * CIN + icz * CINB + ic) * 9 + t];
    }
    for (int idx = tid; idx < IMGS * CINB * HPT * WPAD; idx += 256) {
        int c = idx % WPAD; int t2 = idx / WPAD;
        int r = t2 % HPT; t2 /= HPT;
        int ic = t2 % CINB; int img = t2 / CINB;
        int gr = row0 + r - 1;
        float v = 0.f;
        if (gr >= 0 && gr < H && c >= 1 && c <= W) {
            int ch = icz * CINB + ic;
            v = in[(((size_t)(b0 + img) * CIN + ch) * H + gr) * W + (c - 1)];
            if (BN_IN) v = fmaxf(0.f, fmaf(v, scale[ch], shift[ch]));
        }
        s_in[img * IMG_STRIDE + ic * PLANE + r * WPAD + c] = v;
    }
    __syncthreads();

    const u64* w64 = (const u64*)s_w;

    for (int item = tid; item < ITEMS; item += 256) {
        int gy = item % HS; int t = item / HS;
        int gx = t % G; t /= G;
        int img = t % IMGS; int ocg = t / IMGS;

        u64 acc[4][4];
        #pragma unroll
        for (int px = 0; px < 4; px++)
            #pragma unroll
            for (int op = 0; op < 4; op++) acc[px][op] = 0ull;

        const float* ibase = s_in + img * IMG_STRIDE + gy * WPAD + 4 * gx;
        const u64* wbase = w64 + (size_t)ocg * 4 * 9;

        #pragma unroll 2
        for (int ic = 0; ic < CINB; ic++) {
            const float* ip = ibase + ic * PLANE;
            const u64* wrow = wbase + (size_t)ic * (COUT / 2) * 9;
            #pragma unroll
            for (int r = 0; r < 3; r++) {
                float i0 = ip[r * WPAD + 0], i1 = ip[r * WPAD + 1], i2 = ip[r * WPAD + 2];
                float i3 = ip[r * WPAD + 3], i4 = ip[r * WPAD + 4], i5 = ip[r * WPAD + 5];
                u64 d0 = pack2(i0, i0), d1 = pack2(i1, i1), d2 = pack2(i2, i2);
                u64 d3 = pack2(i3, i3), d4 = pack2(i4, i4), d5 = pack2(i5, i5);
                #pragma unroll
                for (int op = 0; op < 4; op++) {
                    const u64* w9 = wrow + op * 9 + r * 3;
                    u64 w;
                    w = w9[0];
                    acc[0][op] = fma2(d0, w, acc[0][op]);
                    acc[1][op] = fma2(d1, w, acc[1][op]);
                    acc[2][op] = fma2(d2, w, acc[2][op]);
                    acc[3][op] = fma2(d3, w, acc[3][op]);
                    w = w9[1];
                    acc[0][op] = fma2(d1, w, acc[0][op]);
                    acc[1][op] = fma2(d2, w, acc[1][op]);
                    acc[2][op] = fma2(d3, w, acc[2][op]);
                    acc[3][op] = fma2(d4, w, acc[3][op]);
                    w = w9[2];
                    acc[0][op] = fma2(d2, w, acc[0][op]);
                    acc[1][op] = fma2(d3, w, acc[1][op]);
                    acc[2][op] = fma2(d4, w, acc[2][op]);
                    acc[3][op] = fma2(d5, w, acc[3][op]);
                }
            }
        }

        float* outb = out + ((size_t)(b0 + img) * COUT + ocg * 8) * P + (row0 + gy) * W + 4 * gx;
        if (ACCUM) {
            int nvalid = W - 4 * gx; if (nvalid > 4) nvalid = 4;
            #pragma unroll
            for (int op = 0; op < 4; op++) {
                #pragma unroll
                for (int px = 0; px < 4; px++) {
                    if (px < nvalid) {
                        float lo, hi;
                        unpack2(acc[px][op], lo, hi);
                        atomicAdd(&outb[(2 * op) * P + px], lo);
                        atomicAdd(&outb[(2 * op + 1) * P + px], hi);
                    }
                }
            }
        } else if (W % 4 == 0) {
            #pragma unroll
            for (int op = 0; op < 4; op++) {
                float l0, h0, l1, h1, l2, h2, l3, h3;
                unpack2(acc[0][op], l0, h0); unpack2(acc[1][op], l1, h1);
                unpack2(acc[2][op], l2, h2); unpack2(acc[3][op], l3, h3);
                *(float4*)(outb + (2 * op) * P)     = make_float4(l0, l1, l2, l3);
                *(float4*)(outb + (2 * op + 1) * P) = make_float4(h0, h1, h2, h3);
            }
        } else if (W % 2 == 0) {
            #pragma unroll
            for (int op = 0; op < 4; op++) {
                float l0, h0, l1, h1, l2, h2, l3, h3;
                unpack2(acc[0][op], l0, h0); unpack2(acc[1][op], l1, h1);
                unpack2(acc[2][op], l2, h2); unpack2(acc[3][op], l3, h3);
                *(float2*)(outb + (2 * op) * P)     = make_float2(l0, l1);
                *(float2*)(outb + (2 * op + 1) * P) = make_float2(h0, h1);
                if (4 * gx + 3 < W) {
                    *(float2*)(outb + (2 * op) * P + 2)     = make_float2(l2, l3);
                    *(float2*)(outb + (2 * op + 1) * P + 2) = make_float2(h2, h3);
                }
            }
        } else {
            int nvalid = W - 4 * gx; if (nvalid > 4) nvalid = 4;
            #pragma unroll
            for (int op = 0; op < 4; op++) {
                #pragma unroll
                for (int px = 0; px < 4; px++) {
                    if (px < nvalid) {
                        float lo, hi;
                        unpack2(acc[px][op], lo, hi);
                        outb[(2 * op) * P + px]     = lo;
                        outb[(2 * op + 1) * P + px] = hi;
                    }
                }
            }
        }
    }
}

// ---------------- stats + last-block finalize ----------------
__global__ void k_statsfin4(const float* __restrict__ x, float* __restrict__ sum,
                            float* __restrict__ sumsq, int* __restrict__ cnt,
                            const float* __restrict__ gamma, const float* __restrict__ beta,
                            float* __restrict__ scale, float* __restrict__ shift,
                            int C, int HW4, int gmod, float invN) {
    int c = blockIdx.y;
    float s = 0.f, s2 = 0.f;
    int N4 = NB * HW4;
    const float4* xp = (const float4*)x;
    for (int idx = blockIdx.x * blockDim.x + threadIdx.x; idx < N4;
         idx += gridDim.x * blockDim.x) {
        int b = idx / HW4; int p = idx - b * HW4;
        float4 v = xp[(size_t)(b * C + c) * HW4 + p];
        s += (v.x + v.y) + (v.z + v.w);
        s2 = fmaf(v.x, v.x, s2); s2 = fmaf(v.y, v.y, s2);
        s2 = fmaf(v.z, v.z, s2); s2 = fmaf(v.w, v.w, s2);
    }
    s = warp_sum(s); s2 = warp_sum(s2);
    __shared__ float sh[2][8];
    int lane = threadIdx.x & 31, wid = threadIdx.x >> 5;
    if (lane == 0) { sh[0][wid] = s; sh[1][wid] = s2; }
    __syncthreads();
    if (threadIdx.x == 0) {
        float a = 0.f, b2 = 0.f;
        #pragma unroll
        for (int i = 0; i < 8; i++) { a += sh[0][i]; b2 += sh[1][i]; }
        atomicAdd(&sum[c], a); atomicAdd(&sumsq[c], b2);
        __threadfence();
        int t = atomicAdd(&cnt[c], 1);
        if (t == (int)gridDim.x - 1) {
            __threadfence();
            float Ssum = *((volatile float*)&sum[c]);
            float Ssq  = *((volatile float*)&sumsq[c]);
            float mean = Ssum * invN;
            float var  = Ssq * invN - mean * mean;
            float sc = gamma[c % gmod] * rsqrtf(var + 1e-5f);
            scale[c] = sc;
            shift[c] = beta[c % gmod] - mean * sc;
        }
    }
}

__global__ void k_statsfin(const float* __restrict__ x, float* __restrict__ sum,
                           float* __restrict__ sumsq, int* __restrict__ cnt,
                           const float* __restrict__ gamma, const float* __restrict__ beta,
                           float* __restrict__ scale, float* __restrict__ shift,
                           int C, int HW, int gmod, float invN) {
    int c = blockIdx.y;
    float s = 0.f, s2 = 0.f;
    int N = NB * HW;
    for (int idx = blockIdx.x * blockDim.x + threadIdx.x; idx < N;
         idx += gridDim.x * blockDim.x) {
        int b = idx / HW; int p = idx - b * HW;
        float v = x[((size_t)b * C + c) * HW + p];
        s += v; s2 = fmaf(v, v, s2);
    }
    s = warp_sum(s); s2 = warp_sum(s2);
    __shared__ float sh[2][8];
    int lane = threadIdx.x & 31, wid = threadIdx.x >> 5;
    if (lane == 0) { sh[0][wid] = s; sh[1][wid] = s2; }
    __syncthreads();
    if (threadIdx.x == 0) {
        float a = 0.f, b2 = 0.f;
        #pragma unroll
        for (int i = 0; i < 8; i++) { a += sh[0][i]; b2 += sh[1][i]; }
        atomicAdd(&sum[c], a); atomicAdd(&sumsq[c], b2);
        __threadfence();
        int t = atomicAdd(&cnt[c], 1);
        if (t == (int)gridDim.x - 1) {
            __threadfence();
            float Ssum = *((volatile float*)&sum[c]);
            float Ssq  = *((volatile float*)&sumsq[c]);
            float mean = Ssum * invN;
            float var  = Ssq * invN - mean * mean;
            float sc = gamma[c % gmod] * rsqrtf(var + 1e-5f);
            scale[c] = sc;
            shift[c] = beta[c % gmod] - mean * sc;
        }
    }
}

// ---------------- BN + ReLU + 2x2 maxpool ----------------
template<int C, int H, int W, int PAD>
__global__ void k_pool(const float* __restrict__ in, const float* __restrict__ scale,
                       const float* __restrict__ shift, float* __restrict__ out) {
    constexpr int HO = (H + 2 * PAD) / 2, WO = (W + 2 * PAD) / 2;
    int total = NB * C * HO * WO;
    for (int idx = blockIdx.x * blockDim.x + threadIdx.x; idx < total;
         idx += gridDim.x * blockDim.x) {
        int wo = idx % WO; int t = idx / WO;
        int ho = t % HO; t /= HO;
        int c = t % C; int b = t / C;
        const float* p = in + ((size_t)b * C + c) * (H * W);
        float sc = scale[c], sh = shift[c];
        float m = -1e30f;
        int iy0 = ho * 2 - PAD, ix0 = wo * 2 - PAD;
        #pragma unroll
        for (int dy = 0; dy < 2; dy++) {
            int iy = iy0 + dy; if (iy < 0 || iy >= H) continue;
            #pragma unroll
            for (int dx = 0; dx < 2; dx++) {
                int ix = ix0 + dx; if (ix < 0 || ix >= W) continue;
                float v = fmaxf(0.f, fmaf(p[iy * W + ix], sc, sh));
                if (v > m) m = v;
            }
        }
        out[idx] = m;
    }
}

// ---------------- NMS (rotation-minor channel view c = c1*8 + j) ----------------
__global__ void k_nms(const float* __restrict__ x, const float* __restrict__ scale,
                      const float* __restrict__ shift, float* __restrict__ nms_sum) {
    const int HW = 196;
    int total = NB * 4 * HW;
    float local = 0.f;
    for (int idx = blockIdx.x * blockDim.x + threadIdx.x; idx < total;
         idx += gridDim.x * blockDim.x) {
        int p = idx % HW; int t = idx / HW;
        int c1 = t % 4; int b = t / 4;
        const float* base = x + ((size_t)b * 32 + c1 * 8) * HW + p;
        float v[8]; float m = -1e30f;
        #pragma unroll
        for (int j = 0; j < 8; j++) {
            int c = c1 * 8 + j;
            float u = fmaxf(0.f, fmaf(base[j * HW], scale[c], shift[c]));
            v[j] = u; if (u > m) m = u;
        }
        float s = 0.f;
        #pragma unroll
        for (int j = 0; j < 8; j++) if (v[j] != m) s += v[j];
        local += s;
    }
    local = warp_sum(local);
    __shared__ float sh[8];
    int lane = threadIdx.x & 31, wid = threadIdx.x >> 5;
    if (lane == 0) sh[wid] = local;
    __syncthreads();
    if (threadIdx.x == 0) {
        float a = 0.f;
        #pragma unroll
        for (int i = 0; i < 8; i++) a += sh[i];
        atomicAdd(nms_sum, a);
    }
}

// ---------------- conv7 + bias + global maxpool + NMS scalar ----------------
__global__ __launch_bounds__(256)
void k_conv7(const float* __restrict__ in, const float* __restrict__ w7,
             const float* __restrict__ b7, const float* __restrict__ nms_sum,
             float* __restrict__ out, int out_size) {
    __shared__ float s_in[64 * 16];
    __shared__ float s_w[10 * 64 * 16];
    __shared__ float s_res[250];
    __shared__ float s_b[10];
    int b = blockIdx.x, tid = threadIdx.x;
    for (int i = tid; i < 64 * 16; i += 256) s_in[i] = in[(size_t)b * 64 * 16 + i];
    for (int i = tid; i < 10 * 64 * 16; i += 256) s_w[i] = w7[i];
    if (tid < 10) s_b[tid] = b7[tid];
    __syncthreads();

    for (int item = tid; item < 250; item += 256) {
        int oc = item / 25; int pix = item % 25;
        int oy = pix / 5, ox = pix % 5;
        float a = 0.f;
        for (int ic = 0; ic < 64; ic++) {
            const float* ip = s_in + ic * 16;
            const float* wp = s_w + (oc * 64 + ic) * 16;
            #pragma unroll
            for (int ky = 0; ky < 4; ky++) {
                int iy = oy + ky - 2; if (iy < 0 || iy > 3) continue;
                #pragma unroll
                for (int kx = 0; kx < 4; kx++) {
                    int ix = ox + kx - 2; if (ix < 0 || ix > 3) continue;
                    a = fmaf(ip[iy * 4 + ix], wp[ky * 4 + kx], a);
                }
            }
        }
        s_res[item] = a;
    }
    __syncthreads();
    if (tid < 10) {
        float m = -1e30f;
        #pragma unroll
        for (int p = 0; p < 25; p++) m = fmaxf(m, s_res[tid * 25 + p]);
        out[b * 10 + tid] = m + s_b[tid];
    }
    if (b == 0 && tid == 0)
        out[out_size - 1] = nms_sum[0] * (1.0f / 12845056.0f);
}

// ---------------- launch ----------------
extern "C" void kernel_launch(void* const* d_in, const int* in_sizes, int n_in,
                              void* d_out, int out_size) {
    const float* x   = (const float*)d_in[0];
    const float* w1  = (const float*)d_in[1];
    const float* w2  = (const float*)d_in[2];
    const float* w3  = (const float*)d_in[3];
    const float* w4  = (const float*)d_in[4];
    const float* w5  = (const float*)d_in[5];
    const float* w6  = (const float*)d_in[6];
    const float* w7  = (const float*)d_in[7];
    const float* g1  = (const float*)d_in[8];
    const float* b1  = (const float*)d_in[9];
    const float* g2  = (const float*)d_in[10];
    const float* b2  = (const float*)d_in[11];
    const float* g3  = (const float*)d_in[12];
    const float* b3  = (const float*)d_in[13];
    const float* g4  = (const float*)d_in[14];
    const float* b4  = (const float*)d_in[15];
    const float* g5  = (const float*)d_in[16];
    const float* b5  = (const float*)d_in[17];
    const float* g6  = (const float*)d_in[18];
    const float* b6  = (const float*)d_in[19];
    const float* b7  = (const float*)d_in[20];
    float* out = (float*)d_out;

    float *buf1, *buf2, *buf3, *buf4, *buf5, *buf6, *buf7, *buf8, *buf9;
    float *rk1, *rk2, *rk3, *psum, *psumsq, *pscale, *pshift, *pnms;
    int* pcnt;
    cudaGetSymbolAddress((void**)&buf1, g_buf1);
    cudaGetSymbolAddress((void**)&buf2, g_buf2);
    cudaGetSymbolAddress((void**)&buf3, g_buf3);
    cudaGetSymbolAddress((void**)&buf4, g_buf4);
    cudaGetSymbolAddress((void**)&buf5, g_buf5);
    cudaGetSymbolAddress((void**)&buf6, g_buf6);
    cudaGetSymbolAddress((void**)&buf7, g_buf7);
    cudaGetSymbolAddress((void**)&buf8, g_buf8);
    cudaGetSymbolAddress((void**)&buf9, g_buf9);
    cudaGetSymbolAddress((void**)&rk1, g_rk1);
    cudaGetSymbolAddress((void**)&rk2, g_rk2);
    cudaGetSymbolAddress((void**)&rk3, g_rk3);
    cudaGetSymbolAddress((void**)&psum, g_sum);
    cudaGetSymbolAddress((void**)&psumsq, g_sumsq);
    cudaGetSymbolAddress((void**)&pscale, g_scale);
    cudaGetSymbolAddress((void**)&pshift, g_shift);
    cudaGetSymbolAddress((void**)&pcnt, g_cnt);
    cudaGetSymbolAddress((void**)&pnms, g_nms);

    // smem bytes per config
    const int SM1 = (1*(1*30*31)      + 1*16*9)  * 4;   //  4296
    const int SM2 = (1*(16*16*31)     + 16*16*9) * 4;   // 40960
    const int SM3 = (1*(16*16*19)     + 16*32*9) * 4;   // 37888
    const int SM4 = (1*(16*16*19)     + 16*32*9) * 4;   // 37888 (icsplit 2)
    const int SM5 = (2*(16*9*11+8)    + 16*64*9) * 4;   // 49600 (icsplit 2)
    const int SM6 = (2*(16*9*11+8)    + 16*64*9) * 4;   // 49600 (icsplit 4)

    cudaFuncSetAttribute(conv3x3v4<16,16,28,28,14,1,31,0,1,true,false>, cudaFuncAttributeMaxDynamicSharedMemorySize, SM2);
    cudaFuncSetAttribute(conv3x3v4<16,32,14,14,14,1,19,0,1,false,false>,cudaFuncAttributeMaxDynamicSharedMemorySize, SM3);
    cudaFuncSetAttribute(conv3x3v4<32,32,14,14,14,1,19,0,2,true,true>,  cudaFuncAttributeMaxDynamicSharedMemorySize, SM4);
    cudaFuncSetAttribute(conv3x3v4<32,64,7,7,7,2,11,8,2,false,true>,    cudaFuncAttributeMaxDynamicSharedMemorySize, SM5);
    cudaFuncSetAttribute(conv3x3v4<64,64,7,7,7,2,11,8,4,true,true>,     cudaFuncAttributeMaxDynamicSharedMemorySize, SM6);

    const float invN784 = 1.0f / (2048.0f * 784.0f);
    const float invN196 = 1.0f / (2048.0f * 196.0f);
    const float invN49  = 1.0f / (2048.0f * 49.0f);

    k_zero_bufs<<<1024, 256>>>();
    k_build_rk<<<4, 256>>>(w1, w2, w3);

    // conv1 (1->16, 28x28, no split)
    conv3x3v4<1,16,28,28,28,1,31,0,1,false,false><<<dim3(NB,1,1), 256, SM1>>>(x, rk1, nullptr, nullptr, buf1);
    k_statsfin4<<<dim3(64, 16), 256>>>(buf1, psum + ST1, psumsq + ST1, pcnt + ST1,
                                       g1, b1, pscale + ST1, pshift + ST1, 16, 196, 2, invN784);

    // conv2 (16->16, 28x28, H split 2)
    conv3x3v4<16,16,28,28,14,1,31,0,1,true,false><<<dim3(NB,2,1), 256, SM2>>>(buf1, rk2, pscale + ST1, pshift + ST1, buf2);
    k_statsfin4<<<dim3(64, 16), 256>>>(buf2, psum + ST2, psumsq + ST2, pcnt + ST2,
                                       g2, b2, pscale + ST2, pshift + ST2, 16, 196, 2, invN784);

    k_pool<16,28,28,0><<<4096, 256>>>(buf2, pscale + ST2, pshift + ST2, buf3);

    // conv3 (16->32, 14x14)
    conv3x3v4<16,32,14,14,14,1,19,0,1,false,false><<<dim3(NB,1,1), 256, SM3>>>(buf3, rk3, nullptr, nullptr, buf4);
    k_statsfin4<<<dim3(64, 32), 256>>>(buf4, psum + ST3, psumsq + ST3, pcnt + ST3,
                                       g3, b3, pscale + ST3, pshift + ST3, 32, 49, 4, invN196);

    k_nms<<<1024, 256>>>(buf4, pscale + ST3, pshift + ST3, pnms);

    // conv4 (32->32, 14x14, ic split 2, accumulate)
    conv3x3v4<32,32,14,14,14,1,19,0,2,true,true><<<dim3(NB,1,2), 256, SM4>>>(buf4, w4, pscale + ST3, pshift + ST3, buf5);
    k_statsfin4<<<dim3(64, 32), 256>>>(buf5, psum + ST4, psumsq + ST4, pcnt + ST4,
                                       g4, b4, pscale + ST4, pshift + ST4, 32, 49, 32, invN196);

    k_pool<32,14,14,0><<<2048, 256>>>(buf5, pscale + ST4, pshift + ST4, buf6);

    // conv5 (32->64, 7x7, 2 imgs, ic split 2, accumulate)
    conv3x3v4<32,64,7,7,7,2,11,8,2,false,true><<<dim3(NB/2,1,2), 256, SM5>>>(buf6, w5, nullptr, nullptr, buf7);
    k_statsfin<<<dim3(64, 64), 256>>>(buf7, psum + ST5, psumsq + ST5, pcnt + ST5,
                                      g5, b5, pscale + ST5, pshift + ST5, 64, 49, 64, invN49);

    // conv6 (64->64, 7x7, 2 imgs, ic split 4, accumulate)
    conv3x3v4<64,64,7,7,7,2,11,8,4,true,true><<<dim3(NB/2,1,4), 256, SM6>>>(buf7, w6, pscale + ST5, pshift + ST5, buf8);
    k_statsfin<<<dim3(64, 64), 256>>>(buf8, psum + ST6, psumsq + ST6, pcnt + ST6,
                                      g6, b6, pscale + ST6, pshift + ST6, 64, 49, 64, invN49);

    k_pool<64,7,7,1><<<1024, 256>>>(buf8, pscale + ST6, pshift + ST6, buf9);

    k_conv7<<<NB, 256>>>(buf9, w7, b7, pnms, out, out_size);
}